// round 6
// baseline (speedup 1.0000x reference)
#include <cuda_runtime.h>
#include <cuda_bf16.h>

// FastSpeech2 hard duration-based frame->token scalar averaging.
//   d_in[0] frame_scalar      float32 [B, 8192]
//   d_in[1] duration          float32 [B, 1024]
//   d_in[2] frame_scalar_len  int32   [B]
//   d_in[3] duration_len      int32   [B]
// Output: token_scalar float32 [B, 1024] (+ optional duration_len as f32 [B]).
//
// R5: persistent CTAs (3/SM), cp.async double-buffered row pipeline so DRAM
// streams during the scan/gather compute phases. Warp-contiguous layout:
// warp w owns elements [w*1024, (w+1)*1024) -> vectorized LDS.128/STS.128
// in-place prefix scan, no padding, no staging round trip.

#define TFR 8192
#define TTK 1024
#define NTHREADS 256
#define NWARPS 8
#define KITER 8     // 8 iters * 32 lanes * 4 floats = 1024 elements per warp
#define CHT 4       // tokens per thread

__global__ __launch_bounds__(NTHREADS)
void fs2_dur_avg_kernel(const float* __restrict__ frame_scalar,
                        const float* __restrict__ duration,
                        const int*   __restrict__ frame_scalar_len,
                        const int*   __restrict__ duration_len,
                        float*       __restrict__ out,
                        int B, int write_extra)
{
    extern __shared__ float smem[];                 // 2 * TFR floats (ping-pong)
    __shared__ float s_wtot[NWARPS];                // frame warp totals
    __shared__ float s_fwoff[NWARPS];               // frame warp exclusive offsets
    __shared__ float s_dwsum[NWARPS];               // duration warp totals
    __shared__ float s_dwoff[NWARPS];               // duration warp offsets

    const int tid  = threadIdx.x;
    const int lane = tid & 31;
    const int w    = tid >> 5;
    const int stride = gridDim.x;

    const unsigned sm0 = (unsigned)__cvta_generic_to_shared(smem);

    // --- prologue: prefetch first row into buffer 0 ---
    int row = blockIdx.x;
    if (row < B) {
        const float* src = frame_scalar + (size_t)row * TFR;
        #pragma unroll
        for (int k = 0; k < KITER; k++) {
            const int idx = (w << 10) + (k << 7) + (lane << 2);
            asm volatile("cp.async.cg.shared.global [%0], [%1], 16;\n"
                         :: "r"(sm0 + idx * 4), "l"(src + idx));
        }
    }
    asm volatile("cp.async.commit_group;\n");

    int parity = 0;
    for (; row < B; row += stride, parity ^= 1) {
        float* buf = smem + parity * TFR;

        // --- prefetch next row into the other buffer (fire and forget) ---
        {
            const int nxt = row + stride;
            if (nxt < B) {
                const float* src = frame_scalar + (size_t)nxt * TFR;
                const unsigned smn = sm0 + (unsigned)((parity ^ 1) * TFR * 4);
                #pragma unroll
                for (int k = 0; k < KITER; k++) {
                    const int idx = (w << 10) + (k << 7) + (lane << 2);
                    asm volatile("cp.async.cg.shared.global [%0], [%1], 16;\n"
                                 :: "r"(smn + idx * 4), "l"(src + idx));
                }
            }
            asm volatile("cp.async.commit_group;\n");
        }

        // --- independent loads + duration local work while copies fly ---
        const float4 d4 = reinterpret_cast<const float4*>(
                              duration + (size_t)row * TTK)[tid];
        const int   dl = duration_len[row];
        const float fl = (float)frame_scalar_len[row];

        float dv[CHT], p[CHT], d_excl;
        {
            const float din[CHT] = {d4.x, d4.y, d4.z, d4.w};
            const int jbase = tid * CHT;
            #pragma unroll
            for (int k = 0; k < CHT; k++) {
                // round half-to-even (jnp.round), clamp >=0, zero past dlen
                const float r = fmaxf(rintf(din[k]), 0.0f);
                dv[k] = (jbase + k < dl) ? r : 0.0f;
            }
            float run = 0.0f;
            #pragma unroll
            for (int k = 0; k < CHT; k++) { run += dv[k]; p[k] = run; }
            float incl = run;
            #pragma unroll
            for (int d = 1; d < 32; d <<= 1) {
                const float t = __shfl_up_sync(0xffffffffu, incl, d);
                if (lane >= d) incl += t;
            }
            if (lane == 31) s_dwsum[w] = incl;
            d_excl = incl - run;              // exclusive offset within warp
        }

        // --- wait for this row's frame data ---
        asm volatile("cp.async.wait_group 1;\n");
        __syncthreads();

        // --- in-place warp-contiguous inclusive prefix scan ---
        {
            float4* bufv = reinterpret_cast<float4*>(buf);
            float base = 0.0f;
            #pragma unroll
            for (int k = 0; k < KITER; k++) {
                const int g = (w << 8) + (k << 5) + lane;   // float4 index
                float4 v = bufv[g];
                const float s1 = v.x;
                const float s2 = s1 + v.y;
                const float s3 = s2 + v.z;
                const float s4 = s3 + v.w;
                float incl = s4;
                #pragma unroll
                for (int d = 1; d < 32; d <<= 1) {
                    const float t = __shfl_up_sync(0xffffffffu, incl, d);
                    if (lane >= d) incl += t;
                }
                const float excl = base + (incl - s4);
                v.x = excl + s1; v.y = excl + s2;
                v.z = excl + s3; v.w = excl + s4;
                bufv[g] = v;
                base += __shfl_sync(0xffffffffu, incl, 31);
            }
            if (lane == 0) s_wtot[w] = base;
        }
        __syncthreads();

        if (tid == 0) {
            float acc = 0.0f;
            #pragma unroll
            for (int i = 0; i < NWARPS; i++) { s_fwoff[i] = acc; acc += s_wtot[i]; }
            acc = 0.0f;
            #pragma unroll
            for (int i = 0; i < NWARPS; i++) { s_dwoff[i] = acc; acc += s_dwsum[i]; }
        }
        __syncthreads();
        // cfs(e) := sum frame[0..e) = (e==0) ? 0 : buf[e-1] + s_fwoff[(e-1)>>10]

        // --- gather ---
        {
            const float off = s_dwoff[w] + d_excl;
            float4 res;
            float* rp = reinterpret_cast<float*>(&res);
            #pragma unroll
            for (int k = 0; k < CHT; k++) {
                const float cend_raw   = off + p[k];        // cumsum thru token j
                const float cstart_raw = cend_raw - dv[k];  // cumsum thru j-1
                const float endf   = fminf(cend_raw, fl);
                const float startf = fminf(cstart_raw, fl);
                const float dlen_f = endf - startf;         // exact int-valued
                const int e = (int)endf;
                const int s = (int)startf;
                const float cfs_e = (e == 0) ? 0.0f
                                  : buf[e - 1] + s_fwoff[(e - 1) >> 10];
                const float cfs_s = (s == 0) ? 0.0f
                                  : buf[s - 1] + s_fwoff[(s - 1) >> 10];
                const float seg = cfs_e - cfs_s;
                rp[k] = (dlen_f > 0.0f) ? seg / fmaxf(dlen_f, 1.0f) : 0.0f;
            }
            reinterpret_cast<float4*>(out + (size_t)row * TTK)[tid] = res;
        }

        if (write_extra && tid == 0)
            out[(size_t)B * TTK + row] = (float)dl;

        // protect buf (gather reads) and small tables before the next
        // iteration's cp.async / duration-scan writes touch them
        __syncthreads();
    }
}

extern "C" void kernel_launch(void* const* d_in, const int* in_sizes, int n_in,
                              void* d_out, int out_size) {
    const float* frame_scalar     = (const float*)d_in[0];
    const float* duration         = (const float*)d_in[1];
    const int*   frame_scalar_len = (const int*)d_in[2];
    const int*   duration_len     = (const int*)d_in[3];
    float* out = (float*)d_out;

    const int B = in_sizes[2];                        // [B] int32
    const int write_extra = (out_size > B * TTK) ? 1 : 0;

    int dev = 0, nsm = 148;
    cudaGetDevice(&dev);
    cudaDeviceGetAttribute(&nsm, cudaDevAttrMultiProcessorCount, dev);

    int grid = nsm * 3;                               // 3 CTAs/SM (smem-bound)
    if (grid > B) grid = B;

    const int dyn_smem = 2 * TFR * (int)sizeof(float);   // 64 KB ping-pong
    cudaFuncSetAttribute(fs2_dur_avg_kernel,
                         cudaFuncAttributeMaxDynamicSharedMemorySize, dyn_smem);

    fs2_dur_avg_kernel<<<grid, NTHREADS, dyn_smem>>>(
        frame_scalar, duration, frame_scalar_len, duration_len,
        out, B, write_extra);
}

// round 8
// speedup vs baseline: 1.0028x; 1.0028x over previous
#include <cuda_runtime.h>
#include <cuda_bf16.h>

// FastSpeech2 hard duration-based frame->token scalar averaging.
//   d_in[0] frame_scalar      float32 [B, 8192]
//   d_in[1] duration          float32 [B, 1024]
//   d_in[2] frame_scalar_len  int32   [B]
//   d_in[3] duration_len      int32   [B]
// Output: token_scalar float32 [B, 1024] (+ optional duration_len as f32 [B]).
//
// R6/R7: NO frame prefix scan. Each token sums its own (avg-8, max-16 elem)
// segment directly from the smem-staged frame row. Only remaining scan is the
// 1024-token duration cumsum (1 warp-scan + branch-free warp-offset sum).
// Persistent CTAs (3/SM), cp.async double-buffered rows, 2 barriers/row.

#define TFR 8192
#define TTK 1024
#define NTHREADS 256
#define NWARPS 8
#define KITER 8     // 8 float4 cp.asyncs per thread = 8192 floats per CTA
#define CHT 4       // tokens per thread

__global__ __launch_bounds__(NTHREADS)
void fs2_dur_avg_kernel(const float* __restrict__ frame_scalar,
                        const float* __restrict__ duration,
                        const int*   __restrict__ frame_scalar_len,
                        const int*   __restrict__ duration_len,
                        float*       __restrict__ out,
                        int B, int write_extra)
{
    extern __shared__ float smem[];                 // 2 * TFR floats (ping-pong)
    __shared__ float s_dwsum[NWARPS];               // duration warp totals

    const int tid    = threadIdx.x;
    const int lane   = tid & 31;
    const int w      = tid >> 5;
    const int stride = gridDim.x;

    const unsigned sm0 = (unsigned)__cvta_generic_to_shared(smem);

    // --- prologue: prefetch first row into buffer 0 (coalesced 1KB/warp) ---
    int row = blockIdx.x;
    if (row < B) {
        const float* src = frame_scalar + (size_t)row * TFR;
        #pragma unroll
        for (int k = 0; k < KITER; k++) {
            const int idx = (k << 10) + (tid << 2);          // k*1024 + tid*4
            asm volatile("cp.async.cg.shared.global [%0], [%1], 16;\n"
                         :: "r"(sm0 + idx * 4), "l"(src + idx));
        }
    }
    asm volatile("cp.async.commit_group;\n");

    int parity = 0;
    for (; row < B; row += stride, parity ^= 1) {
        const float* buf = smem + parity * TFR;

        // --- prefetch next row into the other buffer (fire and forget) ---
        {
            const int nxt = row + stride;
            if (nxt < B) {
                const float* src = frame_scalar + (size_t)nxt * TFR;
                const unsigned smn = sm0 + (unsigned)((parity ^ 1) * TFR * 4);
                #pragma unroll
                for (int k = 0; k < KITER; k++) {
                    const int idx = (k << 10) + (tid << 2);
                    asm volatile("cp.async.cg.shared.global [%0], [%1], 16;\n"
                                 :: "r"(smn + idx * 4), "l"(src + idx));
                }
            }
            asm volatile("cp.async.commit_group;\n");
        }

        // --- independent loads + duration cumsum while copies fly ---
        const float4 d4 = reinterpret_cast<const float4*>(
                              duration + (size_t)row * TTK)[tid];
        const int   dl = duration_len[row];
        const float fl = (float)frame_scalar_len[row];

        float dv[CHT], p[CHT], d_excl;
        {
            const float din[CHT] = {d4.x, d4.y, d4.z, d4.w};
            const int jbase = tid * CHT;
            #pragma unroll
            for (int k = 0; k < CHT; k++) {
                // round half-to-even (jnp.round), clamp >=0, zero past dlen
                const float r = fmaxf(rintf(din[k]), 0.0f);
                dv[k] = (jbase + k < dl) ? r : 0.0f;
            }
            float run = 0.0f;
            #pragma unroll
            for (int k = 0; k < CHT; k++) { run += dv[k]; p[k] = run; }
            float incl = run;
            #pragma unroll
            for (int d = 1; d < 32; d <<= 1) {
                const float t = __shfl_up_sync(0xffffffffu, incl, d);
                if (lane >= d) incl += t;
            }
            if (lane == 31) s_dwsum[w] = incl;
            d_excl = incl - run;              // exclusive offset within warp
        }

        // --- wait for this row's frame data; make s_dwsum visible ---
        asm volatile("cp.async.wait_group 1;\n");
        __syncthreads();

        // Cross-warp duration offset: branch-free predicated accumulation
        // (broadcast smem reads, exact integer-valued sums, no extra barrier).
        float doff = d_excl;
        #pragma unroll
        for (int i = 0; i < NWARPS - 1; i++) {
            const float take = (i < w) ? 1.0f : 0.0f;
            doff += take * s_dwsum[i];
        }

        // --- gather: direct segment sums from smem ---
        {
            float4 res;
            float* rp = reinterpret_cast<float*>(&res);
            #pragma unroll
            for (int k = 0; k < CHT; k++) {
                const float cend_raw   = doff + p[k];       // cumsum thru token j
                const float cstart_raw = cend_raw - dv[k];  // cumsum thru j-1
                const float endf   = fminf(cend_raw, fl);
                const float startf = fminf(cstart_raw, fl);
                const float dlen_f = endf - startf;         // exact int-valued
                const int e = (int)endf;
                const int s = (int)startf;
                float sum = 0.0f;
                for (int i = s; i < e; i++) sum += buf[i];
                rp[k] = (dlen_f > 0.0f) ? sum / fmaxf(dlen_f, 1.0f) : 0.0f;
            }
            reinterpret_cast<float4*>(out + (size_t)row * TTK)[tid] = res;
        }

        if (write_extra && tid == 0)
            out[(size_t)B * TTK + row] = (float)dl;

        // Protect buf (gather reads) and s_dwsum before next iteration's
        // cp.async / duration-scan writes touch them.
        __syncthreads();
    }
}

extern "C" void kernel_launch(void* const* d_in, const int* in_sizes, int n_in,
                              void* d_out, int out_size) {
    const float* frame_scalar     = (const float*)d_in[0];
    const float* duration         = (const float*)d_in[1];
    const int*   frame_scalar_len = (const int*)d_in[2];
    const int*   duration_len     = (const int*)d_in[3];
    float* out = (float*)d_out;

    const int B = in_sizes[2];                        // [B] int32
    const int write_extra = (out_size > B * TTK) ? 1 : 0;

    int dev = 0, nsm = 148;
    cudaGetDevice(&dev);
    cudaDeviceGetAttribute(&nsm, cudaDevAttrMultiProcessorCount, dev);

    int grid = nsm * 3;                               // 3 CTAs/SM (smem-bound)
    if (grid > B) grid = B;

    const int dyn_smem = 2 * TFR * (int)sizeof(float);   // 64 KB ping-pong
    cudaFuncSetAttribute(fs2_dur_avg_kernel,
                         cudaFuncAttributeMaxDynamicSharedMemorySize, dyn_smem);

    fs2_dur_avg_kernel<<<grid, NTHREADS, dyn_smem>>>(
        frame_scalar, duration, frame_scalar_len, duration_len,
        out, B, write_extra);
}

// round 9
// speedup vs baseline: 1.0617x; 1.0587x over previous
#include <cuda_runtime.h>
#include <cuda_bf16.h>

// FastSpeech2 hard duration-based frame->token scalar averaging.
//   d_in[0] frame_scalar      float32 [B, 8192]
//   d_in[1] duration          float32 [B, 1024]
//   d_in[2] frame_scalar_len  int32   [B]
//   d_in[3] duration_len      int32   [B]
// Output: token_scalar float32 [B, 1024] (+ optional duration_len as f32 [B]).
//
// R9: R4-deferred compute (best measured: padded conflict-free scan, 2-LDS
// gather, 6 CTAs/SM) made persistent, with prefetch.global.L2 of the NEXT
// row's frame+duration lines issued during the current row's compute. L2
// prefetch costs no smem -> occupancy stays 6 CTAs/SM while DRAM streams
// through the compute phases.

#define TFR 8192
#define TTK 1024
#define NTHREADS 256
#define CHF (TFR / NTHREADS)   // 32 frame elements per thread
#define CHF4 (CHF / 4)         // 8 float4 loads per thread
#define CHT (TTK / NTHREADS)   // 4 tokens per thread
#define NWARPS (NTHREADS / 32)

// Padded smem addressing: one extra slot every 32 floats -> conflict-free for
// striped writes, per-thread contiguous-chunk scan, and the random gather.
__device__ __forceinline__ int PAD(int i) { return i + (i >> 5); }
#define CFS_SLOTS (TFR - 1 + ((TFR - 1) >> 5) + 1)   // PAD(8191)+1 = 8447

__global__ __launch_bounds__(NTHREADS, 6)
void fs2_dur_avg_kernel(const float* __restrict__ frame_scalar,
                        const float* __restrict__ duration,
                        const int*   __restrict__ frame_scalar_len,
                        const int*   __restrict__ duration_len,
                        float*       __restrict__ out,
                        int B, int write_extra)
{
    __shared__ float s_cfs[CFS_SLOTS];   // local (per-chunk) inclusive prefixes
    __shared__ float s_toff[NTHREADS];   // exclusive offset of each thread chunk
    __shared__ float s_wsum[NWARPS];
    __shared__ float s_woff[NWARPS];
    __shared__ float s_dwsum[NWARPS];

    const int tid    = threadIdx.x;
    const int lane   = tid & 31;
    const int wid    = tid >> 5;
    const int stride = gridDim.x;

    for (int row = blockIdx.x; row < B; row += stride) {

        // ---------- Phase 1: stage frame row (coalesced float4 LDG) --------
        {
            const float4* fs4 = reinterpret_cast<const float4*>(
                frame_scalar + (size_t)row * TFR);
            #pragma unroll
            for (int k = 0; k < CHF4; k++) {
                const int v4idx = tid + k * NTHREADS;     // coalesced 512B/warp
                const float4 w = fs4[v4idx];
                const int fidx = v4idx * 4;
                s_cfs[PAD(fidx + 0)] = w.x;
                s_cfs[PAD(fidx + 1)] = w.y;
                s_cfs[PAD(fidx + 2)] = w.z;
                s_cfs[PAD(fidx + 3)] = w.w;
            }
        }

        // ---------- L2 prefetch of the NEXT row (no smem, no occupancy cost)
        {
            const int nxt = row + stride;
            if (nxt < B) {
                // frame row: 8192 floats = 256 x 128B lines, one per thread
                const float* pf = frame_scalar + (size_t)nxt * TFR + tid * 32;
                asm volatile("prefetch.global.L2 [%0];" :: "l"(pf));
                // duration row: 1024 floats = 32 lines, warp 0 lanes
                if (wid == 0) {
                    const float* pd = duration + (size_t)nxt * TTK + lane * 32;
                    asm volatile("prefetch.global.L2 [%0];" :: "l"(pd));
                }
            }
        }

        // ---------- duration load + per-thread/warp cumsum (pre-barrier) ---
        const float4 d4 = reinterpret_cast<const float4*>(
                              duration + (size_t)row * TTK)[tid];
        const int   dl = duration_len[row];
        const float fl = (float)frame_scalar_len[row];

        float dv[CHT], p[CHT], d_excl;
        {
            const float din[CHT] = {d4.x, d4.y, d4.z, d4.w};
            const int jbase = tid * CHT;
            #pragma unroll
            for (int k = 0; k < CHT; k++) {
                // round half-to-even (jnp.round), clamp >=0, zero past dlen
                const float r = fmaxf(rintf(din[k]), 0.0f);
                dv[k] = (jbase + k < dl) ? r : 0.0f;
            }
            float run = 0.0f;
            #pragma unroll
            for (int k = 0; k < CHT; k++) { run += dv[k]; p[k] = run; }
            float incl = run;
            #pragma unroll
            for (int d = 1; d < 32; d <<= 1) {
                const float t = __shfl_up_sync(0xffffffffu, incl, d);
                if (lane >= d) incl += t;
            }
            if (lane == 31) s_dwsum[wid] = incl;
            d_excl = incl - run;              // exclusive offset within warp
        }
        __syncthreads();                      // frame staged + s_dwsum visible

        // ---------- Phase 2: local chunk scan + chunk-offset table ---------
        {
            const int base = tid * CHF;
            float run = 0.0f;
            #pragma unroll
            for (int k = 0; k < CHF; k++) {
                const int i = PAD(base + k);          // conflict-free
                run += s_cfs[i];
                s_cfs[i] = run;                       // local inclusive prefix
            }
            const float tot = run;
            float incl = tot;
            #pragma unroll
            for (int d = 1; d < 32; d <<= 1) {
                const float t = __shfl_up_sync(0xffffffffu, incl, d);
                if (lane >= d) incl += t;
            }
            if (lane == 31) s_wsum[wid] = incl;
            __syncthreads();
            if (tid == 0) {
                float acc = 0.0f;
                #pragma unroll
                for (int w = 0; w < NWARPS; w++) { s_woff[w] = acc; acc += s_wsum[w]; }
            }
            __syncthreads();
            s_toff[tid] = s_woff[wid] + (incl - tot); // exclusive chunk offset
        }

        // Cross-warp duration offset: branch-free broadcast reads (exact
        // integer-valued sums), no extra barrier needed for s_dwsum (written
        // before the first __syncthreads above).
        float doff = d_excl;
        #pragma unroll
        for (int i = 0; i < NWARPS - 1; i++) {
            const float take = (i < wid) ? 1.0f : 0.0f;
            doff += take * s_dwsum[i];
        }
        __syncthreads();                      // s_toff visible
        // cfs(e) := sum frame[0..e) =
        //   (e==0) ? 0 : s_cfs[PAD(e-1)] + s_toff[(e-1) >> 5]

        // ---------- Phase 3: gather ----------------------------------------
        {
            float4 res;
            float* rp = reinterpret_cast<float*>(&res);
            #pragma unroll
            for (int k = 0; k < CHT; k++) {
                const float cend_raw   = doff + p[k];       // cumsum thru token j
                const float cstart_raw = cend_raw - dv[k];  // cumsum thru j-1
                const float endf   = fminf(cend_raw, fl);
                const float startf = fminf(cstart_raw, fl);
                const float dlen_f = endf - startf;         // exact int-valued
                const int e = (int)endf;
                const int s = (int)startf;
                const float cfs_e = (e == 0) ? 0.0f
                                  : s_cfs[PAD(e - 1)] + s_toff[(e - 1) >> 5];
                const float cfs_s = (s == 0) ? 0.0f
                                  : s_cfs[PAD(s - 1)] + s_toff[(s - 1) >> 5];
                const float seg = cfs_e - cfs_s;
                rp[k] = (dlen_f > 0.0f) ? seg / fmaxf(dlen_f, 1.0f) : 0.0f;
            }
            reinterpret_cast<float4*>(out + (size_t)row * TTK)[tid] = res;
        }

        if (write_extra && tid == 0)
            out[(size_t)B * TTK + row] = (float)dl;

        __syncthreads();   // protect s_cfs/s_dwsum before next row's writes
    }
}

extern "C" void kernel_launch(void* const* d_in, const int* in_sizes, int n_in,
                              void* d_out, int out_size) {
    const float* frame_scalar     = (const float*)d_in[0];
    const float* duration         = (const float*)d_in[1];
    const int*   frame_scalar_len = (const int*)d_in[2];
    const int*   duration_len     = (const int*)d_in[3];
    float* out = (float*)d_out;

    const int B = in_sizes[2];                        // [B] int32
    const int write_extra = (out_size > B * TTK) ? 1 : 0;

    int dev = 0, nsm = 148;
    cudaGetDevice(&dev);
    cudaDeviceGetAttribute(&nsm, cudaDevAttrMultiProcessorCount, dev);

    int grid = nsm * 6;                               // 6 CTAs/SM (smem-bound)
    if (grid > B) grid = B;

    fs2_dur_avg_kernel<<<grid, NTHREADS>>>(
        frame_scalar, duration, frame_scalar_len, duration_len,
        out, B, write_extra);
}